// round 16
// baseline (speedup 1.0000x reference)
#include <cuda_runtime.h>
#include <cstdint>

#define NBLKu 128u

// ---------------- device scratch ----------------
__device__ float g_xbuf0[16*128*1024];
__device__ float g_xbuf1[16*128*1024];
__device__ float g_gatesin[2*2048*2048];
__device__ float g_WhhEncT[4*512*2048];
__device__ float g_epart[2*16*16*2048];
__device__ float g_hdec[2*16*1024];
__device__ float g_cdec[2*16*1024];
__device__ float g_hd0[16*1024];
__device__ float g_hd1[16*1024];
__device__ float g_demb[16*128*1024];
__device__ float g_preL0[2048*4096];
__device__ float g_WdecT0[2048*4096];
__device__ float g_WdecT1[2048*4096];
__device__ float g_lininT[1024*1024];
__device__ float g_linoutT[2048*1024];
__device__ float g_encW[2048*1024];
__device__ float g_scores[16*128];
__device__ float g_zero[1024];
__device__ float g_op[16*1024];
__device__ float g_cc[16*1024];
__device__ float g_part0[128*4096];
__device__ float g_part1[128*4096];
__device__ float g_lopart[16*16*1024];
__device__ float g_opn[2048*1024];
__device__ unsigned g_barA, g_barG;

// ---------------- helpers ----------------
__device__ __forceinline__ float2 ffma2(float2 a, float2 b, float2 c) {
    unsigned long long ra = *reinterpret_cast<unsigned long long*>(&a);
    unsigned long long rb = *reinterpret_cast<unsigned long long*>(&b);
    unsigned long long rc = *reinterpret_cast<unsigned long long*>(&c);
    unsigned long long rd;
    asm("fma.rn.f32x2 %0, %1, %2, %3;" : "=l"(rd) : "l"(ra), "l"(rb), "l"(rc));
    return *reinterpret_cast<float2*>(&rd);
}
__device__ __forceinline__ float sigf(float x) { return 1.0f / (1.0f + expf(-x)); }
__device__ __forceinline__ float lstm_h(const float* g4, float& c) {
    float cn = sigf(g4[1]) * c + sigf(g4[0]) * tanhf(g4[2]);
    c = cn;
    return sigf(g4[3]) * tanhf(cn);
}
__device__ __forceinline__ unsigned cvt_tf32(float x) {
    unsigned r; asm("cvt.rna.tf32.f32 %0, %1;" : "=r"(r) : "f"(x)); return r;
}
__device__ __forceinline__ void mma_tf32(float* d, const unsigned* a, const unsigned* b) {
    asm("mma.sync.aligned.m16n8k8.row.col.f32.tf32.tf32.f32 "
        "{%0,%1,%2,%3}, {%4,%5,%6,%7}, {%8,%9}, {%0,%1,%2,%3};"
        : "+f"(d[0]), "+f"(d[1]), "+f"(d[2]), "+f"(d[3])
        : "r"(a[0]), "r"(a[1]), "r"(a[2]), "r"(a[3]), "r"(b[0]), "r"(b[1]));
}

__device__ __forceinline__ void gridbar() {
    __syncthreads();
    if (threadIdx.x == 0) {
        unsigned gen;
        asm volatile("ld.volatile.global.u32 %0, [%1];" : "=r"(gen) : "l"(&g_barG));
        unsigned prev;
        asm volatile("atom.release.gpu.global.add.u32 %0, [%1], 1;"
                     : "=r"(prev) : "l"(&g_barA) : "memory");
        if (prev == NBLKu - 1u) {
            asm volatile("st.global.u32 [%0], 0;" :: "l"(&g_barA) : "memory");
            asm volatile("st.release.gpu.global.u32 [%0], %1;"
                         :: "l"(&g_barG), "r"(gen + 1u) : "memory");
        } else {
            unsigned cur;
            while (true) {
                asm volatile("ld.acquire.gpu.global.u32 %0, [%1];"
                             : "=r"(cur) : "l"(&g_barG) : "memory");
                if (cur != gen) break;
                __nanosleep(32);
            }
        }
    }
    __syncthreads();
}

// ---- GEMV core: thread owns 2 n-cols x 16 batches; k sliced over KS lanes ----
// wp: weight ptr at (kbase+ks, ncol); vsp: smem act ptr at row ks (stride 20).
template<int NK, int KS, int LDW>
__device__ __forceinline__ void gemv_core(const float* __restrict__ wp,
                                          const float* __restrict__ vsp,
                                          float2 acc[2][8]) {
    #pragma unroll 8
    for (int k = 0; k < NK; k++) {
        float2 w2 = *(const float2*)(wp + (size_t)k * KS * LDW);
        const float* v = vsp + k * KS * 20;
        float4 q0 = *(const float4*)(v);
        float4 q1 = *(const float4*)(v + 4);
        float4 q2 = *(const float4*)(v + 8);
        float4 q3 = *(const float4*)(v + 12);
        float2 wa = make_float2(w2.x, w2.x), wb = make_float2(w2.y, w2.y);
        acc[0][0] = ffma2(wa, make_float2(q0.x,q0.y), acc[0][0]);
        acc[0][1] = ffma2(wa, make_float2(q0.z,q0.w), acc[0][1]);
        acc[0][2] = ffma2(wa, make_float2(q1.x,q1.y), acc[0][2]);
        acc[0][3] = ffma2(wa, make_float2(q1.z,q1.w), acc[0][3]);
        acc[0][4] = ffma2(wa, make_float2(q2.x,q2.y), acc[0][4]);
        acc[0][5] = ffma2(wa, make_float2(q2.z,q2.w), acc[0][5]);
        acc[0][6] = ffma2(wa, make_float2(q3.x,q3.y), acc[0][6]);
        acc[0][7] = ffma2(wa, make_float2(q3.z,q3.w), acc[0][7]);
        acc[1][0] = ffma2(wb, make_float2(q0.x,q0.y), acc[1][0]);
        acc[1][1] = ffma2(wb, make_float2(q0.z,q0.w), acc[1][1]);
        acc[1][2] = ffma2(wb, make_float2(q1.x,q1.y), acc[1][2]);
        acc[1][3] = ffma2(wb, make_float2(q1.z,q1.w), acc[1][3]);
        acc[1][4] = ffma2(wb, make_float2(q2.x,q2.y), acc[1][4]);
        acc[1][5] = ffma2(wb, make_float2(q2.z,q2.w), acc[1][5]);
        acc[1][6] = ffma2(wb, make_float2(q3.x,q3.y), acc[1][6]);
        acc[1][7] = ffma2(wb, make_float2(q3.z,q3.w), acc[1][7]);
    }
}

// butterfly-reduce over KS lanes, then lane ks writes its disjoint batch rows.
template<int KS>
__device__ __forceinline__ void gemv_reduce_store(float2 acc[2][8], int ks,
                                                  float* __restrict__ base, int ldp) {
    #pragma unroll
    for (int off = 1; off < KS; off <<= 1) {
        #pragma unroll
        for (int c = 0; c < 2; c++)
            #pragma unroll
            for (int p = 0; p < 8; p++) {
                acc[c][p].x += __shfl_xor_sync(0xffffffffu, acc[c][p].x, off);
                acc[c][p].y += __shfl_xor_sync(0xffffffffu, acc[c][p].y, off);
            }
    }
    #pragma unroll
    for (int p = 0; p < 8; p++) {
        bool mine = (KS == 8) ? (p == ks) : ((p >> 1) == ks);
        if (mine) {
            *(float2*)(base + (size_t)(2*p)   * ldp) = make_float2(acc[0][p].x, acc[1][p].x);
            *(float2*)(base + (size_t)(2*p+1) * ldp) = make_float2(acc[0][p].y, acc[1][p].y);
        }
    }
}

// ---------------- prep: transposes + embeds ----------------
__global__ void __launch_bounds__(256) k_prep(
    const float* __restrict__ enc_emb, const float* __restrict__ dec_emb,
    const float* __restrict__ enc_Whh, const float* __restrict__ dec_Wih0,
    const float* __restrict__ dec_Wih_rest, const float* __restrict__ dec_Whh,
    const float* __restrict__ linin_W, const float* __restrict__ linout_W,
    const int* __restrict__ inp, const int* __restrict__ outtok) {
    unsigned id = blockIdx.x;
    int tid = threadIdx.x;
    if (id >= 23552u) {
        if (id < 31744u) {
            int i = (int)(id - 23552u) * 256 + tid;
            int h = i & 1023, tok = i >> 10;
            g_xbuf0[i] = enc_emb[(size_t)inp[tok] * 1024 + h];
        } else {
            int i = (int)(id - 31744u) * 256 + tid;
            int h = i & 1023, bt = i >> 10;
            int b = bt >> 7, t = bt & 127;
            int tk = (t == 0) ? 3 : outtok[b*128 + t - 1];
            g_demb[i] = dec_emb[(size_t)tk * 1024 + h];
        }
        return;
    }
    const float* in; float* out; int R, C, ld, col0; unsigned tile;
    if (id < 4096u)       { unsigned l4 = id >> 10; tile = id & 1023u;
                            in = enc_Whh + (size_t)l4*2048*512; out = g_WhhEncT + (size_t)l4*512*2048;
                            R = 2048; C = 512; ld = 512; col0 = 0; }
    else if (id < 8192u)  { tile = id - 4096u;  in = dec_Wih0;     out = g_WdecT0;
                            R = 4096; C = 1024; ld = 2048; col0 = 1024; }
    else if (id < 12288u) { tile = id - 8192u;  in = dec_Whh;      out = g_WdecT0 + (size_t)1024*4096;
                            R = 4096; C = 1024; ld = 1024; col0 = 0; }
    else if (id < 16384u) { tile = id - 12288u; in = dec_Wih_rest; out = g_WdecT1;
                            R = 4096; C = 1024; ld = 1024; col0 = 0; }
    else if (id < 20480u) { tile = id - 16384u; in = dec_Whh + (size_t)4096*1024; out = g_WdecT1 + (size_t)1024*4096;
                            R = 4096; C = 1024; ld = 1024; col0 = 0; }
    else if (id < 21504u) { tile = id - 20480u; in = linin_W;      out = g_lininT;
                            R = 1024; C = 1024; ld = 1024; col0 = 0; }
    else                  { tile = id - 21504u; in = linout_W;     out = g_linoutT;
                            R = 1024; C = 2048; ld = 2048; col0 = 0; }
    __shared__ float ts[32][33];
    int cbn = C >> 5;
    int cb = ((int)tile % cbn) << 5, rb = ((int)tile / cbn) << 5;
    int tx = tid & 31, ty = tid >> 5;
    #pragma unroll
    for (int i = 0; i < 32; i += 8)
        ts[ty + i][tx] = in[(size_t)(rb + ty + i) * ld + col0 + cb + tx];
    __syncthreads();
    #pragma unroll
    for (int i = 0; i < 32; i += 8)
        out[(size_t)(cb + ty + i) * R + rb + tx] = ts[tx][ty + i];
}

// ---------------- 512-thread fp32 GEMM tile ----------------
__device__ __forceinline__ void gemm512(
    const float* __restrict__ A, int lda,
    const float* __restrict__ W, int ldw,
    const float* __restrict__ bias,
    float* __restrict__ C, int ldc, int K, int mt, int nt) {
    __shared__ float As[16][132];
    __shared__ float Bs[16][132];
    int tid = threadIdx.x;
    int tx = tid & 15, ty = tid >> 4;
    size_t mb = (size_t)mt * 128, nb = (size_t)nt * 128;
    float2 acc[4][4];
    #pragma unroll
    for (int i = 0; i < 4; i++)
        #pragma unroll
        for (int j = 0; j < 4; j++) acc[i][j] = make_float2(0.f, 0.f);
    int sr = tid >> 2, sk = (tid & 3) * 4;
    const float* Ap = A + (mb + sr) * (size_t)lda + sk;
    const float* Wp = W + (nb + sr) * (size_t)ldw + sk;
    for (int k0 = 0; k0 < K; k0 += 16) {
        float4 a = *(const float4*)(Ap + k0);
        float4 w = *(const float4*)(Wp + k0);
        As[sk+0][sr] = a.x; As[sk+1][sr] = a.y; As[sk+2][sr] = a.z; As[sk+3][sr] = a.w;
        Bs[sk+0][sr] = w.x; Bs[sk+1][sr] = w.y; Bs[sk+2][sr] = w.z; Bs[sk+3][sr] = w.w;
        __syncthreads();
        #pragma unroll
        for (int kk = 0; kk < 16; kk++) {
            float4 av  = *(const float4*)&As[kk][ty*4];
            float4 bv0 = *(const float4*)&Bs[kk][tx*8];
            float4 bv1 = *(const float4*)&Bs[kk][tx*8+4];
            float a4[4] = {av.x, av.y, av.z, av.w};
            float2 bpv[4];
            bpv[0] = make_float2(bv0.x, bv0.y); bpv[1] = make_float2(bv0.z, bv0.w);
            bpv[2] = make_float2(bv1.x, bv1.y); bpv[3] = make_float2(bv1.z, bv1.w);
            #pragma unroll
            for (int i = 0; i < 4; i++) {
                float2 ai = make_float2(a4[i], a4[i]);
                #pragma unroll
                for (int j = 0; j < 4; j++) acc[i][j] = ffma2(ai, bpv[j], acc[i][j]);
            }
        }
        __syncthreads();
    }
    float bs[8];
    #pragma unroll
    for (int j = 0; j < 8; j++) bs[j] = bias[nb + tx*8 + j];
    #pragma unroll
    for (int i = 0; i < 4; i++) {
        float* Cp = C + (mb + ty*4 + i) * (size_t)ldc + nb + tx*8;
        *(float4*)Cp       = make_float4(acc[i][0].x + bs[0], acc[i][0].y + bs[1],
                                         acc[i][1].x + bs[2], acc[i][1].y + bs[3]);
        *(float4*)(Cp + 4) = make_float4(acc[i][2].x + bs[4], acc[i][2].y + bs[5],
                                         acc[i][3].x + bs[6], acc[i][3].y + bs[7]);
    }
}

// ---------------- 512-thread tf32 tensor-core GEMM tile ----------------
__device__ __forceinline__ void gemm_mma512(
    const float* __restrict__ A, int lda,
    const float* __restrict__ W, int ldw,
    const float* __restrict__ bias,
    float* __restrict__ C, int ldc, int K, int mt, int nt) {
    __shared__ unsigned Asm[16][132];
    __shared__ unsigned Wsm[16][132];
    int tid = threadIdx.x;
    int wid = tid >> 5, lane = tid & 31;
    int wm = (wid & 3) * 32, wn = (wid >> 2) * 32;
    int qrow = lane >> 2, qk = lane & 3;
    size_t mb = (size_t)mt * 128, nb = (size_t)nt * 128;
    float acc[2][4][4];
    #pragma unroll
    for (int i = 0; i < 2; i++)
        #pragma unroll
        for (int j = 0; j < 4; j++)
            #pragma unroll
            for (int q = 0; q < 4; q++) acc[i][j][q] = 0.f;
    int sr = tid >> 2, sk = (tid & 3) * 4;
    const float* Ap = A + (mb + sr) * (size_t)lda + sk;
    const float* Wp = W + (nb + sr) * (size_t)ldw + sk;
    float4 a = *(const float4*)Ap;
    float4 w = *(const float4*)Wp;
    for (int k0 = 0; k0 < K; k0 += 16) {
        Asm[sk+0][sr] = cvt_tf32(a.x); Asm[sk+1][sr] = cvt_tf32(a.y);
        Asm[sk+2][sr] = cvt_tf32(a.z); Asm[sk+3][sr] = cvt_tf32(a.w);
        Wsm[sk+0][sr] = cvt_tf32(w.x); Wsm[sk+1][sr] = cvt_tf32(w.y);
        Wsm[sk+2][sr] = cvt_tf32(w.z); Wsm[sk+3][sr] = cvt_tf32(w.w);
        __syncthreads();
        if (k0 + 16 < K) {
            a = *(const float4*)(Ap + k0 + 16);
            w = *(const float4*)(Wp + k0 + 16);
        }
        #pragma unroll
        for (int kk = 0; kk < 16; kk += 8) {
            unsigned af[2][4], bf[4][2];
            #pragma unroll
            for (int i = 0; i < 2; i++) {
                int m0 = wm + i*16 + qrow;
                af[i][0] = Asm[kk+qk][m0];
                af[i][1] = Asm[kk+qk][m0+8];
                af[i][2] = Asm[kk+qk+4][m0];
                af[i][3] = Asm[kk+qk+4][m0+8];
            }
            #pragma unroll
            for (int j = 0; j < 4; j++) {
                int n0 = wn + j*8 + qrow;
                bf[j][0] = Wsm[kk+qk][n0];
                bf[j][1] = Wsm[kk+qk+4][n0];
            }
            #pragma unroll
            for (int i = 0; i < 2; i++)
                #pragma unroll
                for (int j = 0; j < 4; j++) mma_tf32(acc[i][j], af[i], bf[j]);
        }
        __syncthreads();
    }
    #pragma unroll
    for (int i = 0; i < 2; i++) {
        #pragma unroll
        for (int j = 0; j < 4; j++) {
            size_t r0 = mb + wm + i*16 + qrow;
            size_t c0 = nb + wn + j*8 + qk*2;
            float2 bv = *(const float2*)(bias + c0);
            *(float2*)(C + r0 * (size_t)ldc + c0) =
                make_float2(acc[i][j][0] + bv.x, acc[i][j][1] + bv.y);
            *(float2*)(C + (r0 + 8) * (size_t)ldc + c0) =
                make_float2(acc[i][j][2] + bv.x, acc[i][j][3] + bv.y);
        }
    }
}

__global__ void __launch_bounds__(512, 2) k_gemmA(
    const float* __restrict__ enc_Wih, const float* __restrict__ enc_b,
    const float* __restrict__ dec_Wih0, const float* __restrict__ dec_b) {
    int id = blockIdx.x;
    if (id < 256)
        gemm512(g_xbuf0, 1024, enc_Wih, 1024, enc_b, g_gatesin, 2048, 1024, id >> 4, id & 15);
    else if (id < 512) {
        int j = id - 256;
        gemm512(g_xbuf0, 1024, enc_Wih + (size_t)2048*1024, 1024, enc_b + 2048,
                g_gatesin + (size_t)2048*2048, 2048, 1024, j >> 4, j & 15);
    } else {
        int j = id - 512;
        gemm_mma512(g_demb, 1024, dec_Wih0, 2048, dec_b, g_preL0, 4096, 1024, j >> 5, j & 31);
    }
}

__global__ void __launch_bounds__(512, 2) k_gemmGen(
    const float* __restrict__ gen_W, const float* __restrict__ gen_b,
    float* __restrict__ logits) {
    gemm_mma512(g_opn, 1024, gen_W, 1024, gen_b, logits, 32000, 1024, blockIdx.y, blockIdx.x);
}

// ---------------- persistent encoder: 128 x 512 ----------------
__global__ void __launch_bounds__(512, 1) k_encAll(
    const float* __restrict__ enc_Wih, const float* __restrict__ enc_b) {
    __shared__ float sb[1280];
    int tid = threadIdx.x, bid = blockIdx.x;
    int d = bid >> 6, nc = (bid >> 3) & 7, kc = bid & 7;
    int ks = tid & 3, ng = tid >> 2;
    int ncol = nc*256 + ng*2;

    for (int l = 0; l < 2; l++) {
        if (l == 1) {
            gridbar();   // xbuf1 complete
            #pragma unroll 1
            for (int tt = 0; tt < 4; tt++) {
                int tile = bid*4 + tt;
                int d2 = tile >> 8, j = tile & 255;
                gemm512(g_xbuf1, 1024, enc_Wih + (size_t)(2 + d2)*2048*1024, 1024,
                        enc_b + (2 + d2)*2048, g_gatesin + (size_t)d2*2048*2048, 2048, 1024,
                        j >> 4, j & 15);
            }
            gridbar();
        }
        const float* WhhT = g_WhhEncT + (size_t)(l*2 + d)*512*2048;
        const float* gin  = g_gatesin + (size_t)d*2048*2048;
        float* xout = l ? g_xbuf0 : g_xbuf1;
        float creg[2] = {0.f, 0.f};

        for (int s = 0; s <= 128; s++) {
            #pragma unroll
            for (int j = 0; j < 2; j++) {
                int i2 = tid + 512*j;
                int k = i2 >> 4, b = i2 & 15;
                int hh = kc*64 + k;
                float v;
                if (s == 0) { v = 0.f; creg[j] = 0.f; }
                else {
                    int sp = s - 1;
                    int sdir = d ? (127 - sp) : sp;
                    const float* gr = gin + ((size_t)b*128 + sdir)*2048;
                    const float* ep = g_epart + (size_t)(sp & 1)*524288 + (size_t)(d*8)*16*2048;
                    float g4[4];
                    #pragma unroll
                    for (int q = 0; q < 4; q++) {
                        int col = q*512 + hh;
                        float x = gr[col];
                        #pragma unroll
                        for (int p = 0; p < 8; p++) x += ep[(size_t)(p*16 + b)*2048 + col];
                        g4[q] = x;
                    }
                    v = lstm_h(g4, creg[j]);
                    if (nc == 0) {
                        xout[((size_t)b*128 + sdir)*1024 + d*512 + hh] = v;
                        if (s == 128) {
                            g_hdec[l*16384 + b*1024 + d*512 + hh] = v;
                            g_cdec[l*16384 + b*1024 + d*512 + hh] = creg[j];
                        }
                    }
                }
                if (s < 128) sb[k*20 + b] = v;
            }
            if (s == 128) break;
            __syncthreads();
            {
                float2 acc[2][8];
                #pragma unroll
                for (int c = 0; c < 2; c++)
                    #pragma unroll
                    for (int p = 0; p < 8; p++) acc[c][p] = make_float2(0.f, 0.f);
                gemv_core<16, 4, 2048>(WhhT + (size_t)(kc*64 + ks)*2048 + ncol, sb + ks*20, acc);
                float* base = g_epart + (size_t)(s & 1)*524288
                              + (size_t)((d*8 + kc)*16)*2048 + ncol;
                gemv_reduce_store<4>(acc, ks, base, 2048);
            }
            gridbar();
        }
    }
    gridbar();   // xbuf0 (enc output) complete
    gemm512(g_xbuf0, 1024, g_lininT, 1024, g_zero, g_encW, 1024, 1024, bid >> 3, bid & 7);
}

// ---------------- persistent decoder: 128 x 512, 7 phases/step ----------------
__global__ void __launch_bounds__(512, 1) k_dec_persist(const float* __restrict__ bias1) {
    __shared__ float sb[5120];
    int tid = threadIdx.x, bid = blockIdx.x;
    int kcA = bid & 7, ncA = bid >> 3;
    int ksA = tid & 3, ngA = tid >> 2;
    int ncolA = ncA*256 + ngA*2;
    int kcG = bid & 15, ncG = bid >> 4;
    int ksG = tid & 7, ngG = tid >> 3;
    int ncolG = ncG*128 + ngG*2;
    int bF = bid >> 3, sg = bid & 7;
    int sb_b = tid >> 5, sb_lane = tid & 31;   // staging: warp per batch

    // cell0 ownership: output index bid*128 + (tid&127)
    int b0i = bid*128 + (tid & 127);
    float cd0 = (tid < 128) ? g_cdec[b0i] : 0.f;
    float cd1f[2];
    cd1f[0] = g_cdec[16384 + bF*1024 + tid];
    cd1f[1] = g_cdec[16384 + bF*1024 + tid + 512];

    for (int t = 0; t < 128; t++) {
        // ---- Phase A: stage [op(t-1) ; hd0(t-1)] chunk, gemv -> part0 ----
        #pragma unroll
        for (int j = 0; j < 8; j++) {
            int kl = j*32 + sb_lane;
            float v;
            if (kcA < 4) {
                v = t ? g_op[sb_b*1024 + kcA*256 + kl] : 0.f;
            } else {
                int hh = kcA*256 - 1024 + kl;
                v = t ? g_hd0[sb_b*1024 + hh] : g_hdec[sb_b*1024 + hh];
            }
            sb[kl*20 + sb_b] = v;
        }
        __syncthreads();
        {
            float2 acc[2][8];
            #pragma unroll
            for (int c = 0; c < 2; c++)
                #pragma unroll
                for (int p = 0; p < 8; p++) acc[c][p] = make_float2(0.f, 0.f);
            gemv_core<64, 4, 4096>(g_WdecT0 + (size_t)(kcA*256 + ksA)*4096 + ncolA,
                                   sb + ksA*20, acc);
            gemv_reduce_store<4>(acc, ksA, g_part0 + (size_t)(kcA*16)*4096 + ncolA, 4096);
        }
        gridbar();
        // ---- Phase B: cell0 (one output per thread, 128/block) ----
        if (tid < 128) {
            int b = b0i >> 10, hh = b0i & 1023;
            const float* pl = g_preL0 + ((size_t)b*128 + t)*4096;
            float g4[4];
            #pragma unroll
            for (int q = 0; q < 4; q++) {
                int col = q*1024 + hh;
                float x = pl[col];
                #pragma unroll
                for (int p = 0; p < 8; p++) x += g_part0[(size_t)(p*16 + b)*4096 + col];
                g4[q] = x;
            }
            g_hd0[b0i] = lstm_h(g4, cd0);
        }
        gridbar();
        // ---- Phase C: stage [hd0(t) ; hd1(t-1)], gemv -> part1 ----
        #pragma unroll
        for (int j = 0; j < 8; j++) {
            int kl = j*32 + sb_lane;
            float v;
            if (kcA < 4) {
                v = g_hd0[sb_b*1024 + kcA*256 + kl];
            } else {
                int hh = kcA*256 - 1024 + kl;
                v = t ? g_hd1[sb_b*1024 + hh] : g_hdec[16384 + sb_b*1024 + hh];
            }
            sb[kl*20 + sb_b] = v;
        }
        __syncthreads();
        {
            float2 acc[2][8];
            #pragma unroll
            for (int c = 0; c < 2; c++)
                #pragma unroll
                for (int p = 0; p < 8; p++) acc[c][p] = make_float2(0.f, 0.f);
            gemv_core<64, 4, 4096>(g_WdecT1 + (size_t)(kcA*256 + ksA)*4096 + ncolA,
                                   sb + ksA*20, acc);
            gemv_reduce_store<4>(acc, ksA, g_part1 + (size_t)(kcA*16)*4096 + ncolA, 4096);
        }
        gridbar();
        // ---- Phase F1: cell1 (per-bF, into smem) + 16 scores per block ----
        #pragma unroll
        for (int j = 0; j < 2; j++) {
            int hh = tid + 512*j;
            float g4[4];
            #pragma unroll
            for (int q = 0; q < 4; q++) {
                int col = q*1024 + hh;
                float x = bias1[col];
                #pragma unroll
                for (int p = 0; p < 8; p++) x += g_part1[(size_t)(p*16 + bF)*4096 + col];
                g4[q] = x;
            }
            float v = lstm_h(g4, cd1f[j]);
            sb[hh] = v;
            if (sg == 0) g_hd1[bF*1024 + hh] = v;
        }
        __syncthreads();
        {
            int w = tid >> 5, lane = tid & 31;
            int s = sg*16 + w;
            const float* er = g_encW + ((size_t)bF*128 + s)*1024;
            float a = 0.f;
            #pragma unroll 8
            for (int k = lane; k < 1024; k += 32) a += er[k] * sb[k];
            #pragma unroll
            for (int o = 16; o; o >>= 1) a += __shfl_xor_sync(0xffffffffu, a, o);
            if (!lane) g_scores[bF*128 + s] = a;
        }
        gridbar();
        // ---- Phase F2: softmax + context ----
        {
            float* sc = sb;
            float* pc = sb + 128;
            if (tid < 128) sc[tid] = g_scores[bF*128 + tid];
            __syncthreads();
            if (tid < 32) {
                float m = -1e30f;
                #pragma unroll
                for (int s = tid; s < 128; s += 32) m = fmaxf(m, sc[s]);
                #pragma unroll
                for (int o = 16; o; o >>= 1) m = fmaxf(m, __shfl_xor_sync(0xffffffffu, m, o));
                float sum = 0.f;
                #pragma unroll
                for (int s = tid; s < 128; s += 32) { float e2 = expf(sc[s]-m); sc[s] = e2; sum += e2; }
                #pragma unroll
                for (int o = 16; o; o >>= 1) sum += __shfl_xor_sync(0xffffffffu, sum, o);
                float inv = 1.f / sum;
                #pragma unroll
                for (int s = tid; s < 128; s += 32) sc[s] *= inv;
            }
            __syncthreads();
            int hoff = tid & 127, squad = tid >> 7;
            int h = sg*128 + hoff;
            const float* e = g_xbuf0 + ((size_t)bF*128 + squad*32)*1024 + h;
            float a = 0.f;
            #pragma unroll 8
            for (int s = 0; s < 32; s++) a += sc[squad*32 + s] * e[(size_t)s*1024];
            pc[tid] = a;
            __syncthreads();
            if (tid < 128)
                g_cc[bF*1024 + sg*128 + tid] = pc[tid] + pc[tid+128] + pc[tid+256] + pc[tid+384];
        }
        gridbar();
        // ---- Phase G: stage [cc ; hd1] chunk, gemv -> lopart ----
        #pragma unroll
        for (int j = 0; j < 4; j++) {
            int kl = j*32 + sb_lane;
            int kg = kcG*128 + kl;
            float v = (kcG < 8) ? g_cc[sb_b*1024 + kg] : g_hd1[sb_b*1024 + kg - 1024];
            sb[kl*20 + sb_b] = v;
        }
        __syncthreads();
        {
            float2 acc[2][8];
            #pragma unroll
            for (int c = 0; c < 2; c++)
                #pragma unroll
                for (int p = 0; p < 8; p++) acc[c][p] = make_float2(0.f, 0.f);
            gemv_core<16, 8, 1024>(g_linoutT + (size_t)(kcG*128 + ksG)*1024 + ncolG,
                                   sb + ksG*20, acc);
            gemv_reduce_store<8>(acc, ksG, g_lopart + (size_t)(kcG*16)*1024 + ncolG, 1024);
        }
        gridbar();
        // ---- Phase H: opn = tanh(sum), op ----
        if (tid < 128) {
            int gi2 = bid*128 + tid;
            int b = gi2 >> 10, hh = gi2 & 1023;
            float v = 0.f;
            #pragma unroll
            for (int p = 0; p < 16; p++) v += g_lopart[(size_t)(p*16 + b)*1024 + hh];
            float o = tanhf(v);
            g_op[b*1024 + hh] = o;
            g_opn[((size_t)b*128 + t)*1024 + hh] = o;
        }
        gridbar();
    }
}

// ---------------- host ----------------
extern "C" void kernel_launch(void* const* d_in, const int* in_sizes, int n_in,
                              void* d_out, int out_size) {
    const float* enc_emb      = (const float*)d_in[0];
    const float* dec_emb      = (const float*)d_in[1];
    const float* enc_Wih      = (const float*)d_in[2];
    const float* enc_Whh      = (const float*)d_in[3];
    const float* enc_b        = (const float*)d_in[4];
    const float* dec_Wih0     = (const float*)d_in[5];
    const float* dec_Wih_rest = (const float*)d_in[6];
    const float* dec_Whh      = (const float*)d_in[7];
    const float* dec_b        = (const float*)d_in[8];
    const float* linin_W      = (const float*)d_in[9];
    const float* linout_W     = (const float*)d_in[10];
    const float* gen_W        = (const float*)d_in[11];
    const float* gen_b        = (const float*)d_in[12];
    const int*   inp          = (const int*)d_in[13];
    const int*   outtok       = (const int*)d_in[14];
    float* logits = (float*)d_out;

    // 0: prep
    k_prep<<<39936, 256>>>(enc_emb, dec_emb, enc_Whh, dec_Wih0, dec_Wih_rest,
                           dec_Whh, linin_W, linout_W, inp, outtok);
    // 1: enc layer-0 gates (fp32) + preL0 (tf32)
    k_gemmA<<<1024, 512>>>(enc_Wih, enc_b, dec_Wih0, dec_b);
    // 2: encoder (both layers + L1 gates + encW)
    k_encAll<<<128, 512>>>(enc_Wih, enc_b);
    // 3: decoder
    k_dec_persist<<<128, 512>>>(dec_b + 4096);
    // 4: generator (tf32 tensor cores)
    k_gemmGen<<<dim3(250, 16), 512>>>(gen_W, gen_b, logits);
}